// round 13
// baseline (speedup 1.0000x reference)
#include <cuda_runtime.h>
#include <cuda_fp16.h>
#include <cstdint>

#define Bq   8
#define Nq   2048
#define DIN  128
#define DOUT 64
#define PIT  132    // fp32 smem pitch (k_proj)
#define PITH 136    // half smem pitch (k_gat)
#define PXH  136    // half pitch for k_proj xp staging

__device__ __half g_xpT[Bq * DOUT * Nq];  // projected features, half, [b][d][n]
__device__ float  g_es[Bq * Nq];
__device__ float  g_ed[Bq * Nq];

static __device__ __forceinline__ float to_tf32(float x) {
    uint32_t r;
    asm("cvt.rna.tf32.f32 %0, %1;" : "=r"(r) : "f"(x));
    return __uint_as_float(r);
}
static __device__ __forceinline__ uint32_t smem_u32(const void* p) {
    uint32_t a;
    asm("{ .reg .u64 t; cvta.to.shared.u64 t, %1; cvt.u32.u64 %0, t; }"
        : "=r"(a) : "l"(p));
    return a;
}
static __device__ __forceinline__ void cp16(uint32_t dst, const void* src) {
    asm volatile("cp.async.cg.shared.global [%0], [%1], 16;"
                 :: "r"(dst), "l"(src) : "memory");
}
#define CP_COMMIT() asm volatile("cp.async.commit_group;" ::: "memory")
#define CP_WAIT0()  asm volatile("cp.async.wait_group 0;" ::: "memory")

// tf32: D += A(16x8) * B(8x8)
static __device__ __forceinline__ void mma8(float* c, const uint32_t* a,
                                            uint32_t b0, uint32_t b1) {
    asm volatile(
        "mma.sync.aligned.m16n8k8.row.col.f32.tf32.tf32.f32 "
        "{%0,%1,%2,%3}, {%4,%5,%6,%7}, {%8,%9}, {%0,%1,%2,%3};"
        : "+f"(c[0]), "+f"(c[1]), "+f"(c[2]), "+f"(c[3])
        : "r"(a[0]), "r"(a[1]), "r"(a[2]), "r"(a[3]), "r"(b0), "r"(b1));
}
// fp16: D += A(16x16) * B(16x8), fp32 accum
static __device__ __forceinline__ void mma16(float* c, const uint32_t* a,
                                             uint32_t b0, uint32_t b1) {
    asm volatile(
        "mma.sync.aligned.m16n8k16.row.col.f32.f16.f16.f32 "
        "{%0,%1,%2,%3}, {%4,%5,%6,%7}, {%8,%9}, {%0,%1,%2,%3};"
        : "+f"(c[0]), "+f"(c[1]), "+f"(c[2]), "+f"(c[3])
        : "r"(a[0]), "r"(a[1]), "r"(a[2]), "r"(a[3]), "r"(b0), "r"(b1));
}

#define BAR_SYNC(id)   asm volatile("bar.sync %0, 256;"   :: "r"(id) : "memory")
#define BAR_ARRIVE(id) asm volatile("bar.arrive %0, 256;" :: "r"(id) : "memory")

// ---------------------------------------------------------------------------
// Kernel 1: xp = x @ W^T + b via tf32 mma.sync (unchanged).
// ---------------------------------------------------------------------------
#define PJ_AS   0
#define PJ_WS   (128 * PIT)
#define PJ_BS   (PJ_WS + 64 * PIT)
#define PJ_ASR  (PJ_BS + 64)
#define PJ_ADR  (PJ_ASR + 64)
#define PJ_ESH  (PJ_ADR + 64)
#define PJ_EDH  (PJ_ESH + 256)
#define PJ_XPH  (PJ_EDH + 256)
#define PJ_SIZE ((PJ_XPH + 32 * PXH) * 4)

__global__ void __launch_bounds__(256, 1)
k_proj(const float* __restrict__ x, const float* __restrict__ W,
       const float* __restrict__ bvec, const float* __restrict__ a) {
    extern __shared__ float sh[];
    float* AS  = sh + PJ_AS;
    float* WS  = sh + PJ_WS;
    float* bsh = sh + PJ_BS;
    float* asr = sh + PJ_ASR;
    float* adr = sh + PJ_ADR;
    float* esh = sh + PJ_ESH;
    float* edh = sh + PJ_EDH;
    __half* xph = (__half*)(sh + PJ_XPH);

    int tid = threadIdx.x, wid = tid >> 5, lid = tid & 31;
    int g = lid >> 2, tg = lid & 3;
    int row0 = blockIdx.x << 7;

    {
        int r = tid & 127, half = tid >> 7;
        const float4* src = (const float4*)(x + (size_t)(row0 + r) * DIN + half * 64);
        float* dst = AS + r * PIT + half * 64;
        #pragma unroll
        for (int i = 0; i < 16; i++) {
            float4 v = src[i];
            v.x = to_tf32(v.x); v.y = to_tf32(v.y);
            v.z = to_tf32(v.z); v.w = to_tf32(v.w);
            ((float4*)dst)[i] = v;
        }
    }
    {
        int d = tid & 63, q = tid >> 6;
        const float4* src = (const float4*)(W + (size_t)d * DIN + q * 32);
        float* dst = WS + d * PIT + q * 32;
        #pragma unroll
        for (int i = 0; i < 8; i++) {
            float4 v = src[i];
            v.x = to_tf32(v.x); v.y = to_tf32(v.y);
            v.z = to_tf32(v.z); v.w = to_tf32(v.w);
            ((float4*)dst)[i] = v;
        }
    }
    if (tid < 64) {
        bsh[tid] = bvec[tid];
        asr[tid] = a[tid];
        adr[tid] = a[DOUT + tid];
    }
    __syncthreads();

    float acc[2][4][4];
    #pragma unroll
    for (int t = 0; t < 2; t++)
        #pragma unroll
        for (int j = 0; j < 4; j++)
            #pragma unroll
            for (int c = 0; c < 4; c++) acc[t][j][c] = 0.f;

    int gm = wid >> 1, h = wid & 1;
    const float* Abase = AS + (32 * gm + g) * PIT + tg;
    const float* Bbase = WS + (32 * h + g) * PIT + tg;

    #pragma unroll
    for (int ks = 0; ks < 16; ks++) {
        int kb = ks * 8;
        uint32_t A[2][4];
        #pragma unroll
        for (int t = 0; t < 2; t++) {
            const float* ap = Abase + t * 16 * PIT + kb;
            A[t][0] = __float_as_uint(ap[0]);
            A[t][1] = __float_as_uint(ap[8 * PIT]);
            A[t][2] = __float_as_uint(ap[4]);
            A[t][3] = __float_as_uint(ap[8 * PIT + 4]);
        }
        #pragma unroll
        for (int j = 0; j < 4; j++) {
            const float* bp = Bbase + j * 8 * PIT + kb;
            uint32_t B0 = __float_as_uint(bp[0]);
            uint32_t B1 = __float_as_uint(bp[4]);
            mma8(acc[0][j], A[0], B0, B1);
            mma8(acc[1][j], A[1], B0, B1);
        }
    }

    #pragma unroll
    for (int t = 0; t < 2; t++) {
        #pragma unroll
        for (int rw = 0; rw < 2; rw++) {
            int m = 32 * gm + g + 16 * t + 8 * rw;
            float es = 0.f, ed = 0.f;
            #pragma unroll
            for (int j = 0; j < 4; j++) {
                int d = 32 * h + 8 * j + 2 * tg;
                float f0 = acc[t][j][2 * rw]     + bsh[d];
                float f1 = acc[t][j][2 * rw + 1] + bsh[d + 1];
                es += f0 * asr[d] + f1 * asr[d + 1];
                ed += f0 * adr[d] + f1 * adr[d + 1];
                xph[(size_t)d * PXH + m]       = __float2half_rn(f0);
                xph[(size_t)(d + 1) * PXH + m] = __float2half_rn(f1);
            }
            es += __shfl_xor_sync(0xffffffffu, es, 1);
            es += __shfl_xor_sync(0xffffffffu, es, 2);
            ed += __shfl_xor_sync(0xffffffffu, ed, 1);
            ed += __shfl_xor_sync(0xffffffffu, ed, 2);
            if (tg == 0) { esh[h * 128 + m] = es; edh[h * 128 + m] = ed; }
        }
    }
    __syncthreads();
    {
        int b = row0 >> 11, nloc = row0 & (Nq - 1);
        int d = tid >> 2, c = tid & 3;
        const uint4* src = (const uint4*)(xph + (size_t)d * PXH + c * 32);
        uint4* dst = (uint4*)(g_xpT + ((size_t)b * DOUT + d) * Nq + nloc + c * 32);
        #pragma unroll
        for (int i = 0; i < 4; i++) dst[i] = src[i];
    }
    if (tid < 128) {
        g_es[row0 + tid] = esh[tid] + esh[128 + tid];
        g_ed[row0 + tid] = edh[tid] + edh[128 + tid];
    }
}

// ---------------------------------------------------------------------------
// Kernel 2: half-size CTAs for 2-CTA/SM co-residency. MT=64 rows, 256 threads
// (warps 0-3 = fp16 MMA consumers 32m x 32d; warps 4-7 = producers).
// Double-buffered P/XT (~85KB SMEM). Same numerics as R8.
// ---------------------------------------------------------------------------
#define MT        64
#define GPS_STR   (MT * PITH * 2)        // 17408
#define GXT_STR   (64 * PITH * 2)        // 17408
#define GPS0      0
#define GXT0      (2 * GPS_STR)          // 34816
#define GE1_OFF   (GXT0 + 2 * GXT_STR)   // 69632
#define GEA_OFF   (GE1_OFF + 8192)       // 77824
#define GS1_OFF   (GEA_OFF + 8192)       // 86016
#define GSA_OFF   (GS1_OFF + 256)        // 86272
#define GDS_OFF   (GSA_OFF + 256)        // 86528
#define GA_SIZE   (GDS_OFF + 256)        // 86784 (~84.8KB -> 2 CTAs/SM)

__global__ void __launch_bounds__(256, 2)
k_gat(const int* __restrict__ adj, float* __restrict__ out) {
    extern __shared__ char smc[];
    float* E1n = (float*)(smc + GE1_OFF);
    float* Ean = (float*)(smc + GEA_OFF);
    float* Es1 = (float*)(smc + GS1_OFF);
    float* Esa = (float*)(smc + GSA_OFF);
    float* dsh = (float*)(smc + GDS_OFF);
    uint32_t smb = smem_u32(smc);

    int tid = threadIdx.x, wid = tid >> 5, lid = tid & 31;
    int g = lid >> 2, tg = lid & 3;
    int b  = blockIdx.x >> 5;
    int m0 = (blockIdx.x & 31) << 6;

    // ---- exp tables (S = 1/256 folded into row tables) ----
    {
        const float* edb = g_ed + b * Nq;
        #pragma unroll
        for (int i = 0; i < 8; i++) {
            int n = tid + 256 * i;
            float v = edb[n];
            E1n[n] = __expf(v);
            Ean[n] = __expf(0.2f * v);
        }
        if (tid < MT) {
            float v = g_es[b * Nq + m0 + tid];
            Es1[tid] = __expf(v) * 0.00390625f;
            Esa[tid] = __expf(0.2f * v) * 0.00390625f;
        }
    }
    __syncthreads();

    if (wid >= 4) {
        // =================== PRODUCER (warps 4-7) ===================
        int j = tid - 128;               // 0..127
        int p = wid - 4;                 // 0..3
        const int*    adjb = adj + (size_t)b * Nq * Nq + (size_t)m0 * Nq + 4 * lid;
        const __half* gxT  = g_xpT + (size_t)b * DOUT * Nq;
        float dsum[16];
        #pragma unroll
        for (int i = 0; i < 16; i++) dsum[i] = 0.f;

        // XT cp.async mapping: thread j covers d-row jd, 128B half jh
        int jd = j >> 1, jh = j & 1;
        const __half* xsrc0 = gxT + (size_t)jd * Nq + jh * 64;
        uint32_t xdst0 = smb + GXT0 + jd * (PITH * 2) + jh * 128;

        int buf = 0;
        #pragma unroll 1
        for (int t = 0; t < 16; t++) {
            int n0 = t << 7;
            if (t >= 2) BAR_SYNC(3 + buf);           // consumers done with buf

            // XT tile t -> SMEM via cp.async (zero registers)
            {
                uint32_t xd = xdst0 + buf * GXT_STR;
                const __half* xs = xsrc0 + n0;
                #pragma unroll
                for (int i = 0; i < 8; i++) cp16(xd + i * 16, xs + i * 8);
            }
            CP_COMMIT();

            float4 e1 = *(const float4*)(E1n + n0 + 4 * lid);
            float4 ea = *(const float4*)(Ean + n0 + 4 * lid);
            __half* PSb = (__half*)(smc + GPS0 + buf * GPS_STR);

            #pragma unroll
            for (int it = 0; it < 16; it++) {
                int m = (it << 2) + p;
                int4 av = *(const int4*)(adjb + (size_t)m * Nq + n0);
                float e1m = Es1[m], eam = Esa[m];
                float p0 = av.x ? fmaxf(e1m * e1.x, eam * ea.x) : 0.f;
                float p1 = av.y ? fmaxf(e1m * e1.y, eam * ea.y) : 0.f;
                float p2 = av.z ? fmaxf(e1m * e1.z, eam * ea.z) : 0.f;
                float p3 = av.w ? fmaxf(e1m * e1.w, eam * ea.w) : 0.f;
                __half2 h01 = __floats2half2_rn(p0, p1);
                __half2 h23 = __floats2half2_rn(p2, p3);
                float2 f01 = __half22float2(h01);
                float2 f23 = __half22float2(h23);
                dsum[it] += (f01.x + f01.y) + (f23.x + f23.y);
                uint2 pk;
                pk.x = *(uint32_t*)&h01;
                pk.y = *(uint32_t*)&h23;
                *(uint2*)(PSb + (size_t)m * PITH + 4 * lid) = pk;
            }
            CP_WAIT0();                               // XT tile t landed
            BAR_ARRIVE(1 + buf);                      // tile t ready
            buf ^= 1;
        }

        #pragma unroll
        for (int it = 0; it < 16; it++) {
            float v = dsum[it];
            v += __shfl_xor_sync(0xffffffffu, v, 16);
            v += __shfl_xor_sync(0xffffffffu, v, 8);
            v += __shfl_xor_sync(0xffffffffu, v, 4);
            v += __shfl_xor_sync(0xffffffffu, v, 2);
            v += __shfl_xor_sync(0xffffffffu, v, 1);
            if (lid == 0) dsh[(it << 2) + p] = v;
        }
        __syncthreads();
    } else {
        // =================== CONSUMER (warps 0-3) ===================
        float acc[2][4][4];
        #pragma unroll
        for (int mt = 0; mt < 2; mt++)
            #pragma unroll
            for (int jj = 0; jj < 4; jj++)
                #pragma unroll
                for (int c = 0; c < 4; c++) acc[mt][jj][c] = 0.f;

        int gm = wid >> 1, dg = wid & 1;
        int buf = 0;
        #pragma unroll 1
        for (int t = 0; t < 16; t++) {
            const __half* PS = (const __half*)(smc + GPS0 + buf * GPS_STR);
            const __half* XT = (const __half*)(smc + GXT0 + buf * GXT_STR);
            const __half* Abase = PS + (32 * gm + g) * PITH + 2 * tg;
            const __half* Bbase = XT + (32 * dg + g) * PITH + 2 * tg;

            BAR_SYNC(1 + buf);               // tile t ready

            #pragma unroll
            for (int ks = 0; ks < 8; ks++) {
                int kb = ks * 16;
                uint32_t A[2][4];
                #pragma unroll
                for (int mt = 0; mt < 2; mt++) {
                    const __half* ap = Abase + mt * 16 * PITH + kb;
                    A[mt][0] = *(const uint32_t*)(ap);
                    A[mt][1] = *(const uint32_t*)(ap + 8 * PITH);
                    A[mt][2] = *(const uint32_t*)(ap + 8);
                    A[mt][3] = *(const uint32_t*)(ap + 8 * PITH + 8);
                }
                #pragma unroll
                for (int jj = 0; jj < 4; jj++) {
                    const __half* bp = Bbase + jj * 8 * PITH + kb;
                    uint32_t B0 = *(const uint32_t*)(bp);
                    uint32_t B1 = *(const uint32_t*)(bp + 8);
                    mma16(acc[0][jj], A[0], B0, B1);
                    mma16(acc[1][jj], A[1], B0, B1);
                }
            }
            if (t < 14) BAR_ARRIVE(3 + buf); // buffer free
            buf ^= 1;
        }
        __syncthreads();

        // ---- normalize + write ----
        float* ob = out + ((size_t)b * Nq + m0) * DOUT;
        #pragma unroll
        for (int mt = 0; mt < 2; mt++) {
            #pragma unroll
            for (int rw = 0; rw < 2; rw++) {
                int m = 32 * gm + 16 * mt + g + 8 * rw;
                float inv = 1.0f / dsh[m];
                #pragma unroll
                for (int jj = 0; jj < 4; jj++) {
                    float2 o = make_float2(acc[mt][jj][2 * rw] * inv,
                                           acc[mt][jj][2 * rw + 1] * inv);
                    *(float2*)(ob + (size_t)m * DOUT + 32 * dg + 8 * jj + 2 * tg) = o;
                }
            }
        }
    }
}

// ---------------------------------------------------------------------------
extern "C" void kernel_launch(void* const* d_in, const int* in_sizes, int n_in,
                              void* d_out, int out_size) {
    const float* x    = (const float*)d_in[0];
    const int*   adj  = (const int*)d_in[1];
    const float* W    = (const float*)d_in[2];
    const float* bvec = (const float*)d_in[3];
    const float* a    = (const float*)d_in[4];
    float* out = (float*)d_out;

    cudaFuncSetAttribute(k_proj, cudaFuncAttributeMaxDynamicSharedMemorySize, PJ_SIZE);
    cudaFuncSetAttribute(k_gat,  cudaFuncAttributeMaxDynamicSharedMemorySize, GA_SIZE);

    k_proj<<<Bq * Nq / 128, 256, PJ_SIZE>>>(x, W, bvec, a);
    k_gat<<<Bq * (Nq / 64), 256, GA_SIZE>>>(adj, out);
}

// round 14
// speedup vs baseline: 1.1469x; 1.1469x over previous
#include <cuda_runtime.h>
#include <cuda_fp16.h>
#include <cstdint>

#define Bq   8
#define Nq   2048
#define DIN  128
#define DOUT 64
#define PIT  132    // fp32 smem pitch (k_proj)
#define PITH 136    // half smem pitch (k_gat)
#define PXH  136    // half pitch for k_proj xp staging

__device__ __half g_xpT[Bq * DOUT * Nq];  // projected features, half, [b][d][n]
__device__ float  g_es[Bq * Nq];
__device__ float  g_ed[Bq * Nq];

static __device__ __forceinline__ float to_tf32(float x) {
    uint32_t r;
    asm("cvt.rna.tf32.f32 %0, %1;" : "=r"(r) : "f"(x));
    return __uint_as_float(r);
}

// tf32: D += A(16x8) * B(8x8)
static __device__ __forceinline__ void mma8(float* c, const uint32_t* a,
                                            uint32_t b0, uint32_t b1) {
    asm volatile(
        "mma.sync.aligned.m16n8k8.row.col.f32.tf32.tf32.f32 "
        "{%0,%1,%2,%3}, {%4,%5,%6,%7}, {%8,%9}, {%0,%1,%2,%3};"
        : "+f"(c[0]), "+f"(c[1]), "+f"(c[2]), "+f"(c[3])
        : "r"(a[0]), "r"(a[1]), "r"(a[2]), "r"(a[3]), "r"(b0), "r"(b1));
}
// fp16: D += A(16x16) * B(16x8), fp32 accum
static __device__ __forceinline__ void mma16(float* c, const uint32_t* a,
                                             uint32_t b0, uint32_t b1) {
    asm volatile(
        "mma.sync.aligned.m16n8k16.row.col.f32.f16.f16.f32 "
        "{%0,%1,%2,%3}, {%4,%5,%6,%7}, {%8,%9}, {%0,%1,%2,%3};"
        : "+f"(c[0]), "+f"(c[1]), "+f"(c[2]), "+f"(c[3])
        : "r"(a[0]), "r"(a[1]), "r"(a[2]), "r"(a[3]), "r"(b0), "r"(b1));
}

#define BAR_SYNC(id)   asm volatile("bar.sync %0, 512;"   :: "r"(id) : "memory")
#define BAR_ARRIVE(id) asm volatile("bar.arrive %0, 512;" :: "r"(id) : "memory")

// ---------------------------------------------------------------------------
// Kernel 1: xp = x @ W^T + b via tf32 mma.sync; epilogue computes es/ed,
// stages xp (half) in SMEM, then writes g_xpT with coalesced stores.
// ---------------------------------------------------------------------------
#define PJ_AS   0
#define PJ_WS   (128 * PIT)
#define PJ_BS   (PJ_WS + 64 * PIT)
#define PJ_ASR  (PJ_BS + 64)
#define PJ_ADR  (PJ_ASR + 64)
#define PJ_ESH  (PJ_ADR + 64)
#define PJ_EDH  (PJ_ESH + 256)
#define PJ_XPH  (PJ_EDH + 256)
#define PJ_SIZE ((PJ_XPH + 32 * PXH) * 4)

__global__ void __launch_bounds__(256, 1)
k_proj(const float* __restrict__ x, const float* __restrict__ W,
       const float* __restrict__ bvec, const float* __restrict__ a) {
    extern __shared__ float sh[];
    float* AS  = sh + PJ_AS;
    float* WS  = sh + PJ_WS;
    float* bsh = sh + PJ_BS;
    float* asr = sh + PJ_ASR;
    float* adr = sh + PJ_ADR;
    float* esh = sh + PJ_ESH;
    float* edh = sh + PJ_EDH;
    __half* xph = (__half*)(sh + PJ_XPH);

    int tid = threadIdx.x, wid = tid >> 5, lid = tid & 31;
    int g = lid >> 2, tg = lid & 3;
    int row0 = blockIdx.x << 7;

    {
        int r = tid & 127, half = tid >> 7;
        const float4* src = (const float4*)(x + (size_t)(row0 + r) * DIN + half * 64);
        float* dst = AS + r * PIT + half * 64;
        #pragma unroll
        for (int i = 0; i < 16; i++) {
            float4 v = src[i];
            v.x = to_tf32(v.x); v.y = to_tf32(v.y);
            v.z = to_tf32(v.z); v.w = to_tf32(v.w);
            ((float4*)dst)[i] = v;
        }
    }
    {
        int d = tid & 63, q = tid >> 6;
        const float4* src = (const float4*)(W + (size_t)d * DIN + q * 32);
        float* dst = WS + d * PIT + q * 32;
        #pragma unroll
        for (int i = 0; i < 8; i++) {
            float4 v = src[i];
            v.x = to_tf32(v.x); v.y = to_tf32(v.y);
            v.z = to_tf32(v.z); v.w = to_tf32(v.w);
            ((float4*)dst)[i] = v;
        }
    }
    if (tid < 64) {
        bsh[tid] = bvec[tid];
        asr[tid] = a[tid];
        adr[tid] = a[DOUT + tid];
    }
    __syncthreads();

    float acc[2][4][4];
    #pragma unroll
    for (int t = 0; t < 2; t++)
        #pragma unroll
        for (int j = 0; j < 4; j++)
            #pragma unroll
            for (int c = 0; c < 4; c++) acc[t][j][c] = 0.f;

    int gm = wid >> 1, h = wid & 1;
    const float* Abase = AS + (32 * gm + g) * PIT + tg;
    const float* Bbase = WS + (32 * h + g) * PIT + tg;

    #pragma unroll
    for (int ks = 0; ks < 16; ks++) {
        int kb = ks * 8;
        uint32_t A[2][4];
        #pragma unroll
        for (int t = 0; t < 2; t++) {
            const float* ap = Abase + t * 16 * PIT + kb;
            A[t][0] = __float_as_uint(ap[0]);
            A[t][1] = __float_as_uint(ap[8 * PIT]);
            A[t][2] = __float_as_uint(ap[4]);
            A[t][3] = __float_as_uint(ap[8 * PIT + 4]);
        }
        #pragma unroll
        for (int j = 0; j < 4; j++) {
            const float* bp = Bbase + j * 8 * PIT + kb;
            uint32_t B0 = __float_as_uint(bp[0]);
            uint32_t B1 = __float_as_uint(bp[4]);
            mma8(acc[0][j], A[0], B0, B1);
            mma8(acc[1][j], A[1], B0, B1);
        }
    }

    #pragma unroll
    for (int t = 0; t < 2; t++) {
        #pragma unroll
        for (int rw = 0; rw < 2; rw++) {
            int m = 32 * gm + g + 16 * t + 8 * rw;
            float es = 0.f, ed = 0.f;
            #pragma unroll
            for (int j = 0; j < 4; j++) {
                int d = 32 * h + 8 * j + 2 * tg;
                float f0 = acc[t][j][2 * rw]     + bsh[d];
                float f1 = acc[t][j][2 * rw + 1] + bsh[d + 1];
                es += f0 * asr[d] + f1 * asr[d + 1];
                ed += f0 * adr[d] + f1 * adr[d + 1];
                xph[(size_t)d * PXH + m]       = __float2half_rn(f0);
                xph[(size_t)(d + 1) * PXH + m] = __float2half_rn(f1);
            }
            es += __shfl_xor_sync(0xffffffffu, es, 1);
            es += __shfl_xor_sync(0xffffffffu, es, 2);
            ed += __shfl_xor_sync(0xffffffffu, ed, 1);
            ed += __shfl_xor_sync(0xffffffffu, ed, 2);
            if (tg == 0) { esh[h * 128 + m] = es; edh[h * 128 + m] = ed; }
        }
    }
    __syncthreads();
    {
        int b = row0 >> 11, nloc = row0 & (Nq - 1);
        int d = tid >> 2, c = tid & 3;
        const uint4* src = (const uint4*)(xph + (size_t)d * PXH + c * 32);
        uint4* dst = (uint4*)(g_xpT + ((size_t)b * DOUT + d) * Nq + nloc + c * 32);
        #pragma unroll
        for (int i = 0; i < 4; i++) dst[i] = src[i];
    }
    if (tid < 128) {
        g_es[row0 + tid] = esh[tid] + esh[128 + tid];
        g_ed[row0 + tid] = edh[tid] + edh[128 + tid];
    }
}

// ---------------------------------------------------------------------------
// Kernel 2: EXACT R8 configuration (best measured: 45.6us).
// 512 threads: warps 0-7 = fp16 MMA consumers (32m x 32d), warps 8-15 =
// producers (adj LDG + scaled P-build + XT reg staging + denominators).
// Triple-buffered P/XT; named barriers full(1..3)/free(4..6).
// P scaled by S=1/256 folded into row exp tables; denominators sum exactly
// what the MMA sees.
// ---------------------------------------------------------------------------
#define GPS_STRIDE 34816                 // 128*PITH*2 bytes
#define GXT_STRIDE 17408                 // 64*PITH*2 bytes
#define GXT_BASE   (3 * GPS_STRIDE)
#define GE1_OFF    (GXT_BASE + 3 * GXT_STRIDE)
#define GEA_OFF    (GE1_OFF + 8192)
#define GS1_OFF    (GEA_OFF + 8192)
#define GSA_OFF    (GS1_OFF + 512)
#define GDS_OFF    (GSA_OFF + 512)
#define GA_SIZE    (GDS_OFF + 512)

__global__ void __launch_bounds__(512, 1)
k_gat(const int* __restrict__ adj, float* __restrict__ out) {
    extern __shared__ char smc[];
    float* E1n = (float*)(smc + GE1_OFF);
    float* Ean = (float*)(smc + GEA_OFF);
    float* Es1 = (float*)(smc + GS1_OFF);
    float* Esa = (float*)(smc + GSA_OFF);
    float* dsh = (float*)(smc + GDS_OFF);

    int tid = threadIdx.x, wid = tid >> 5, lid = tid & 31;
    int g = lid >> 2, tg = lid & 3;
    int b  = blockIdx.x >> 4;
    int m0 = (blockIdx.x & 15) << 7;

    // ---- exp tables (S = 1/256 folded into row tables) ----
    {
        const float* edb = g_ed + b * Nq;
        #pragma unroll
        for (int i = 0; i < 4; i++) {
            int n = tid + 512 * i;
            float v = edb[n];
            E1n[n] = __expf(v);
            Ean[n] = __expf(0.2f * v);
        }
        if (tid < 128) {
            float v = g_es[b * Nq + m0 + tid];
            Es1[tid] = __expf(v) * 0.00390625f;
            Esa[tid] = __expf(0.2f * v) * 0.00390625f;
        }
    }
    __syncthreads();

    if (wid >= 8) {
        // =================== PRODUCER ===================
        int p = wid - 8;
        const int*    adjb = adj + (size_t)b * Nq * Nq + (size_t)m0 * Nq;
        const __half* gxT  = g_xpT + (size_t)b * DOUT * Nq;
        float dsum[16];
        #pragma unroll
        for (int i = 0; i < 16; i++) dsum[i] = 0.f;

        for (int t = 0; t < 16; t++) {
            int n0 = t << 7;
            int buf = t % 3;
            __half* PS = (__half*)(smc + buf * GPS_STRIDE);
            __half* XT = (__half*)(smc + GXT_BASE + buf * GXT_STRIDE);

            if (t >= 3) BAR_SYNC(4 + buf);   // wait: consumers done with t-3

            // XT loads: warp-per-row (uint2 = 4 halves), coalesced 256B rows
            uint2 xtv[8];
            #pragma unroll
            for (int ps = 0; ps < 8; ps++) {
                int row = ps * 8 + p;
                xtv[ps] = ((const uint2*)(gxT + (size_t)row * Nq + n0))[lid];
            }

            float4 e1 = *(const float4*)(E1n + n0 + 4 * lid);
            float4 ea = *(const float4*)(Ean + n0 + 4 * lid);

            // P build (scaled, half2-packed); dsum sums exactly what MMA sees
            #pragma unroll
            for (int it = 0; it < 16; it++) {
                int m = (it << 3) + p;
                float e1m = Es1[m], eam = Esa[m];
                int4 av = *(const int4*)(adjb + (size_t)m * Nq + n0 + 4 * lid);
                float p0 = av.x ? fmaxf(e1m * e1.x, eam * ea.x) : 0.f;
                float p1 = av.y ? fmaxf(e1m * e1.y, eam * ea.y) : 0.f;
                float p2 = av.z ? fmaxf(e1m * e1.z, eam * ea.z) : 0.f;
                float p3 = av.w ? fmaxf(e1m * e1.w, eam * ea.w) : 0.f;
                __half2 h01 = __floats2half2_rn(p0, p1);
                __half2 h23 = __floats2half2_rn(p2, p3);
                float2 f01 = __half22float2(h01);
                float2 f23 = __half22float2(h23);
                dsum[it] += (f01.x + f01.y) + (f23.x + f23.y);
                uint2 pk;
                pk.x = *(uint32_t*)&h01;
                pk.y = *(uint32_t*)&h23;
                *(uint2*)(PS + (size_t)m * PITH + 4 * lid) = pk;
            }
            #pragma unroll
            for (int ps = 0; ps < 8; ps++) {
                int row = ps * 8 + p;
                *(uint2*)(XT + (size_t)row * PITH + 4 * lid) = xtv[ps];
            }
            BAR_ARRIVE(1 + buf);             // signal: tile t ready
        }

        #pragma unroll
        for (int it = 0; it < 16; it++) {
            float v = dsum[it];
            v += __shfl_xor_sync(0xffffffffu, v, 16);
            v += __shfl_xor_sync(0xffffffffu, v, 8);
            v += __shfl_xor_sync(0xffffffffu, v, 4);
            v += __shfl_xor_sync(0xffffffffu, v, 2);
            v += __shfl_xor_sync(0xffffffffu, v, 1);
            if (lid == 0) dsh[(it << 3) + p] = v;
        }
        __syncthreads();
    } else {
        // =================== CONSUMER ===================
        float acc[2][4][4];
        #pragma unroll
        for (int mt = 0; mt < 2; mt++)
            #pragma unroll
            for (int j = 0; j < 4; j++)
                #pragma unroll
                for (int c = 0; c < 4; c++) acc[mt][j][c] = 0.f;

        int gm = wid >> 1, dg = wid & 1;

        for (int t = 0; t < 16; t++) {
            int buf = t % 3;
            const __half* PS = (const __half*)(smc + buf * GPS_STRIDE);
            const __half* XT = (const __half*)(smc + GXT_BASE + buf * GXT_STRIDE);
            const __half* Abase = PS + (32 * gm + g) * PITH + 2 * tg;
            const __half* Bbase = XT + (32 * dg + g) * PITH + 2 * tg;

            BAR_SYNC(1 + buf);               // wait: tile t ready

            #pragma unroll
            for (int ks = 0; ks < 8; ks++) {
                int kb = ks * 16;
                uint32_t A[2][4];
                #pragma unroll
                for (int mt = 0; mt < 2; mt++) {
                    const __half* ap = Abase + mt * 16 * PITH + kb;
                    A[mt][0] = *(const uint32_t*)(ap);
                    A[mt][1] = *(const uint32_t*)(ap + 8 * PITH);
                    A[mt][2] = *(const uint32_t*)(ap + 8);
                    A[mt][3] = *(const uint32_t*)(ap + 8 * PITH + 8);
                }
                #pragma unroll
                for (int j = 0; j < 4; j++) {
                    const __half* bp = Bbase + j * 8 * PITH + kb;
                    uint32_t B0 = *(const uint32_t*)(bp);
                    uint32_t B1 = *(const uint32_t*)(bp + 8);
                    mma16(acc[0][j], A[0], B0, B1);
                    mma16(acc[1][j], A[1], B0, B1);
                }
            }
            if (t < 13) BAR_ARRIVE(4 + buf); // signal: buffer free
        }
        __syncthreads();

        // ---- normalize + write ----
        float* ob = out + ((size_t)b * Nq + m0) * DOUT;
        #pragma unroll
        for (int mt = 0; mt < 2; mt++) {
            #pragma unroll
            for (int rw = 0; rw < 2; rw++) {
                int m = 32 * gm + 16 * mt + g + 8 * rw;
                float inv = 1.0f / dsh[m];
                #pragma unroll
                for (int j = 0; j < 4; j++) {
                    float2 o = make_float2(acc[mt][j][2 * rw] * inv,
                                           acc[mt][j][2 * rw + 1] * inv);
                    *(float2*)(ob + (size_t)m * DOUT + 32 * dg + 8 * j + 2 * tg) = o;
                }
            }
        }
    }
}

// ---------------------------------------------------------------------------
extern "C" void kernel_launch(void* const* d_in, const int* in_sizes, int n_in,
                              void* d_out, int out_size) {
    const float* x    = (const float*)d_in[0];
    const int*   adj  = (const int*)d_in[1];
    const float* W    = (const float*)d_in[2];
    const float* bvec = (const float*)d_in[3];
    const float* a    = (const float*)d_in[4];
    float* out = (float*)d_out;

    cudaFuncSetAttribute(k_proj, cudaFuncAttributeMaxDynamicSharedMemorySize, PJ_SIZE);
    cudaFuncSetAttribute(k_gat,  cudaFuncAttributeMaxDynamicSharedMemorySize, GA_SIZE);

    k_proj<<<Bq * Nq / 128, 256, PJ_SIZE>>>(x, W, bvec, a);
    k_gat<<<Bq * (Nq / 128), 512, GA_SIZE>>>(adj, out);
}